// round 4
// baseline (speedup 1.0000x reference)
#include <cuda_runtime.h>
#include <cstddef>

#define N_NODES 50000
#define N_EDGES 800000

// ---------------- scratch (device globals: alloc-free rule) ----------------
__device__ float g_agg1[(size_t)N_NODES * 64];
__device__ float g_h1  [(size_t)N_NODES * 128];
__device__ float g_agg2[(size_t)N_NODES * 128];
__device__ int   g_is64;
__device__ int   g_deg[N_NODES];
__device__ int   g_off[N_NODES + 1];
__device__ int   g_pos[N_NODES];
__device__ int   g_srcs[N_EDGES];

// ---------------- dtype detection + deg zero ----------------
__global__ void detect_kernel(const unsigned int* __restrict__ p) {
    __shared__ int found;
    if (threadIdx.x == 0) found = 0;
    __syncthreads();
    for (int i = threadIdx.x; i < 4096; i += blockDim.x)
        if (p[2 * i + 1] != 0u) found = 1;
    __syncthreads();
    if (threadIdx.x == 0) g_is64 = found ? 0 : 1;
}

__global__ void zero_deg_kernel() {
    int i = blockIdx.x * blockDim.x + threadIdx.x;
    if (i < N_NODES) g_deg[i] = 0;
}

// ---------------- edge index fetch helper ----------------
__device__ __forceinline__ int load_idx(const void* ei, long long pos) {
    if (g_is64) return (int)__ldg((const long long*)ei + pos);
    return __ldg((const int*)ei + pos);
}

// ---------------- CSR build: histogram, scan, fill ----------------
__global__ void __launch_bounds__(256) hist_kernel(const void* __restrict__ ei) {
    int e = blockIdx.x * blockDim.x + threadIdx.x;
    if (e >= N_EDGES) return;
    int dst = load_idx(ei, (long long)N_EDGES + e);
    atomicAdd(&g_deg[dst], 1);
}

__global__ void __launch_bounds__(1024) scan_kernel() {
    __shared__ int part[1024];
    const int t = threadIdx.x;
    const int CH = (N_NODES + 1023) / 1024;       // 49
    int start = t * CH;
    int end = start + CH; if (end > N_NODES) end = N_NODES;
    int s = 0;
    for (int i = start; i < end; i++) s += g_deg[i];
    part[t] = s;
    __syncthreads();
    // Hillis-Steele inclusive scan
    for (int d = 1; d < 1024; d <<= 1) {
        int v = (t >= d) ? part[t - d] : 0;
        __syncthreads();
        part[t] += v;
        __syncthreads();
    }
    int run = (t == 0) ? 0 : part[t - 1];
    for (int i = start; i < end; i++) {
        g_off[i] = run;
        g_pos[i] = run;
        run += g_deg[i];
    }
    if (t == 1023) g_off[N_NODES] = N_EDGES;
}

__global__ void __launch_bounds__(256) fill_kernel(const void* __restrict__ ei) {
    int e = blockIdx.x * blockDim.x + threadIdx.x;
    if (e >= N_EDGES) return;
    int src = load_idx(ei, e);
    int dst = load_idx(ei, (long long)N_EDGES + e);
    int p = atomicAdd(&g_pos[dst], 1);
    g_srcs[p] = src;
}

// ---------------- CSR aggregation: gather-only, no atomics ----------------
// L = C/4 lanes per node; each lane owns one float4 column, loops edges.
template <int C>
__global__ void __launch_bounds__(256)
agg_csr_kernel(const float* __restrict__ feat, float* __restrict__ agg) {
    constexpr int L = C / 4;
    int gt = blockIdx.x * blockDim.x + threadIdx.x;
    int node = gt / L;
    int lane = gt % L;
    if (node >= N_NODES) return;

    int beg = g_off[node];
    int end = g_off[node + 1];
    const float4* fp = reinterpret_cast<const float4*>(feat);

    float4 a0 = make_float4(0.f, 0.f, 0.f, 0.f);
    float4 a1 = make_float4(0.f, 0.f, 0.f, 0.f);
    float4 a2 = make_float4(0.f, 0.f, 0.f, 0.f);
    float4 a3 = make_float4(0.f, 0.f, 0.f, 0.f);

    int j = beg;
    for (; j + 4 <= end; j += 4) {
        int s0 = __ldg(&g_srcs[j + 0]);
        int s1 = __ldg(&g_srcs[j + 1]);
        int s2 = __ldg(&g_srcs[j + 2]);
        int s3 = __ldg(&g_srcs[j + 3]);
        float4 v0 = __ldg(fp + (size_t)s0 * L + lane);
        float4 v1 = __ldg(fp + (size_t)s1 * L + lane);
        float4 v2 = __ldg(fp + (size_t)s2 * L + lane);
        float4 v3 = __ldg(fp + (size_t)s3 * L + lane);
        a0.x += v0.x; a0.y += v0.y; a0.z += v0.z; a0.w += v0.w;
        a1.x += v1.x; a1.y += v1.y; a1.z += v1.z; a1.w += v1.w;
        a2.x += v2.x; a2.y += v2.y; a2.z += v2.z; a2.w += v2.w;
        a3.x += v3.x; a3.y += v3.y; a3.z += v3.z; a3.w += v3.w;
    }
    for (; j < end; j++) {
        int s0 = __ldg(&g_srcs[j]);
        float4 v0 = __ldg(fp + (size_t)s0 * L + lane);
        a0.x += v0.x; a0.y += v0.y; a0.z += v0.z; a0.w += v0.w;
    }
    float4 r;
    r.x = (a0.x + a1.x) + (a2.x + a3.x);
    r.y = (a0.y + a1.y) + (a2.y + a3.y);
    r.z = (a0.z + a1.z) + (a2.z + a3.z);
    r.w = (a0.w + a1.w) + (a2.w + a3.w);
    reinterpret_cast<float4*>(agg)[(size_t)node * L + lane] = r;
}

// ---------------- fused GIN MLP (unchanged from R3) ----------------
template <int CIN, int H, int COUT, bool RELU_OUT, int NODES>
__global__ void __launch_bounds__(512)
mlp_kernel(const float* __restrict__ x, const float* __restrict__ agg,
           const float* __restrict__ epsp,
           const float* __restrict__ Wa, const float* __restrict__ ba,
           const float* __restrict__ Wb, const float* __restrict__ bb,
           float* __restrict__ out) {
    constexpr int NPT = NODES / 32;
    constexpr int MIDS = H + 4;
    extern __shared__ float s[];
    float* Was = s;
    float* Wbs = Was + CIN * H;
    float* bas = Wbs + H * COUT;
    float* bbs = bas + H;
    float* ins = bbs + COUT;
    float* mid = ins + NODES * CIN;

    const int tid = threadIdx.x;

    for (int i = tid; i < CIN * H / 4; i += 512)
        reinterpret_cast<float4*>(Was)[i] = reinterpret_cast<const float4*>(Wa)[i];
    for (int i = tid; i < H * COUT / 4; i += 512)
        reinterpret_cast<float4*>(Wbs)[i] = reinterpret_cast<const float4*>(Wb)[i];
    if (tid < H) bas[tid] = ba[tid];
    else if (tid >= 128 && tid < 128 + COUT) bbs[tid - 128] = bb[tid - 128];

    const float epsf = 1.0f + __ldg(epsp);
    const int n0 = blockIdx.x * NODES;

    {
        constexpr int C4 = CIN / 4;
        for (int i = tid; i < NODES * C4; i += 512) {
            int n = i / C4, c4 = i - n * C4;
            int gn = n0 + n;
            float4 v = make_float4(0.f, 0.f, 0.f, 0.f);
            if (gn < N_NODES) {
                size_t g = (size_t)gn * C4 + c4;
                float4 xv = reinterpret_cast<const float4*>(x)[g];
                float4 av = reinterpret_cast<const float4*>(agg)[g];
                v.x = fmaf(epsf, xv.x, av.x);
                v.y = fmaf(epsf, xv.y, av.y);
                v.z = fmaf(epsf, xv.z, av.z);
                v.w = fmaf(epsf, xv.w, av.w);
            }
            reinterpret_cast<float4*>(ins)[n * C4 + c4] = v;
        }
    }
    __syncthreads();

    const int tx = tid & 15;
    const int ty = tid >> 4;

    {
        float acc[NPT][8];
        #pragma unroll
        for (int i = 0; i < NPT; i++)
            #pragma unroll
            for (int j = 0; j < 8; j++) acc[i][j] = 0.f;

        #pragma unroll 8
        for (int k = 0; k < CIN; k++) {
            float a[NPT];
            #pragma unroll
            for (int i = 0; i < NPT; i++) a[i] = ins[(ty * NPT + i) * CIN + k];
            float4 w0 = *reinterpret_cast<float4*>(&Was[k * H + tx * 8]);
            float4 w1 = *reinterpret_cast<float4*>(&Was[k * H + tx * 8 + 4]);
            float w[8] = {w0.x, w0.y, w0.z, w0.w, w1.x, w1.y, w1.z, w1.w};
            #pragma unroll
            for (int i = 0; i < NPT; i++)
                #pragma unroll
                for (int j = 0; j < 8; j++) acc[i][j] = fmaf(a[i], w[j], acc[i][j]);
        }
        #pragma unroll
        for (int i = 0; i < NPT; i++) {
            float4 v0, v1;
            v0.x = fmaxf(acc[i][0] + bas[tx * 8 + 0], 0.f);
            v0.y = fmaxf(acc[i][1] + bas[tx * 8 + 1], 0.f);
            v0.z = fmaxf(acc[i][2] + bas[tx * 8 + 2], 0.f);
            v0.w = fmaxf(acc[i][3] + bas[tx * 8 + 3], 0.f);
            v1.x = fmaxf(acc[i][4] + bas[tx * 8 + 4], 0.f);
            v1.y = fmaxf(acc[i][5] + bas[tx * 8 + 5], 0.f);
            v1.z = fmaxf(acc[i][6] + bas[tx * 8 + 6], 0.f);
            v1.w = fmaxf(acc[i][7] + bas[tx * 8 + 7], 0.f);
            float* row = &mid[(ty * NPT + i) * MIDS + tx * 8];
            reinterpret_cast<float4*>(row)[0] = v0;
            reinterpret_cast<float4*>(row)[1] = v1;
        }
    }
    __syncthreads();

    {
        constexpr int CPT = COUT / 16;
        float acc[NPT][CPT];
        #pragma unroll
        for (int i = 0; i < NPT; i++)
            #pragma unroll
            for (int j = 0; j < CPT; j++) acc[i][j] = 0.f;

        #pragma unroll 8
        for (int k = 0; k < H; k++) {
            float a[NPT];
            #pragma unroll
            for (int i = 0; i < NPT; i++) a[i] = mid[(ty * NPT + i) * MIDS + k];
            float w[CPT];
            #pragma unroll
            for (int q = 0; q < CPT / 4; q++) {
                float4 wq = *reinterpret_cast<float4*>(&Wbs[k * COUT + tx * CPT + q * 4]);
                w[q * 4 + 0] = wq.x; w[q * 4 + 1] = wq.y;
                w[q * 4 + 2] = wq.z; w[q * 4 + 3] = wq.w;
            }
            #pragma unroll
            for (int i = 0; i < NPT; i++)
                #pragma unroll
                for (int j = 0; j < CPT; j++) acc[i][j] = fmaf(a[i], w[j], acc[i][j]);
        }
        #pragma unroll
        for (int i = 0; i < NPT; i++) {
            int gn = n0 + ty * NPT + i;
            if (gn < N_NODES) {
                #pragma unroll
                for (int j = 0; j < CPT; j++) {
                    float v = acc[i][j] + bbs[tx * CPT + j];
                    if (RELU_OUT) v = v > 0.f ? v : 0.f;
                    out[(size_t)gn * COUT + tx * CPT + j] = v;
                }
            }
        }
    }
}

// ---------------- launch ----------------
extern "C" void kernel_launch(void* const* d_in, const int* in_sizes, int n_in,
                              void* d_out, int out_size) {
    const float* x    = (const float*)d_in[0];
    const void*  ei   = d_in[1];
    const float* W1   = (const float*)d_in[2];
    const float* b1   = (const float*)d_in[3];
    const float* W2   = (const float*)d_in[4];
    const float* b2   = (const float*)d_in[5];
    const float* eps1 = (const float*)d_in[6];
    const float* W3   = (const float*)d_in[7];
    const float* b3   = (const float*)d_in[8];
    const float* W4   = (const float*)d_in[9];
    const float* b4   = (const float*)d_in[10];
    const float* eps2 = (const float*)d_in[11];
    float* out = (float*)d_out;

    const size_t smem1 = 49920 * sizeof(float);
    const size_t smem2 = 41408 * sizeof(float);
    cudaFuncSetAttribute(mlp_kernel<64, 128, 128, true, 128>,
                         cudaFuncAttributeMaxDynamicSharedMemorySize, (int)smem1);
    cudaFuncSetAttribute(mlp_kernel<128, 128, 64, false, 64>,
                         cudaFuncAttributeMaxDynamicSharedMemorySize, (int)smem2);

    float* agg1; cudaGetSymbolAddress((void**)&agg1, g_agg1);
    float* h1;   cudaGetSymbolAddress((void**)&h1,   g_h1);
    float* agg2; cudaGetSymbolAddress((void**)&agg2, g_agg2);

    // ---- CSR build (once per call, reused by both layers) ----
    detect_kernel<<<1, 256>>>((const unsigned int*)ei);
    zero_deg_kernel<<<(N_NODES + 255) / 256, 256>>>();
    hist_kernel<<<(N_EDGES + 255) / 256, 256>>>(ei);
    scan_kernel<<<1, 1024>>>();
    fill_kernel<<<(N_EDGES + 255) / 256, 256>>>(ei);

    // ---- layer 1 ----
    agg_csr_kernel<64><<<(N_NODES * 16 + 255) / 256, 256>>>(x, agg1);
    mlp_kernel<64, 128, 128, true, 128><<<(N_NODES + 127) / 128, 512, smem1>>>(
        x, agg1, eps1, W1, b1, W2, b2, h1);

    // ---- layer 2 ----
    agg_csr_kernel<128><<<(N_NODES * 32 + 255) / 256, 256>>>(h1, agg2);
    mlp_kernel<128, 128, 64, false, 64><<<(N_NODES + 63) / 64, 512, smem2>>>(
        h1, agg2, eps2, W3, b3, W4, b4, out);
}

// round 5
// speedup vs baseline: 1.1909x; 1.1909x over previous
#include <cuda_runtime.h>
#include <cstddef>

#define N_NODES 50000
#define N_EDGES 800000
#define NB_SCAN 196   // ceil(50000/256)

// ---------------- scratch (device globals: alloc-free rule) ----------------
__device__ float g_agg1[(size_t)N_NODES * 64];
__device__ float g_h1  [(size_t)N_NODES * 128];
__device__ float g_agg2[(size_t)N_NODES * 128];
__device__ int   g_is64;
__device__ int   g_deg[N_NODES];
__device__ int   g_off[N_NODES + 1];
__device__ int   g_pos[N_NODES];
__device__ int   g_srcs[N_EDGES];
__device__ int   g_bsum[256];
__device__ int   g_bpre[256];

// ---------------- dtype detection + deg zero ----------------
__global__ void detect_kernel(const unsigned int* __restrict__ p) {
    __shared__ int found;
    if (threadIdx.x == 0) found = 0;
    __syncthreads();
    for (int i = threadIdx.x; i < 4096; i += blockDim.x)
        if (p[2 * i + 1] != 0u) found = 1;
    __syncthreads();
    if (threadIdx.x == 0) g_is64 = found ? 0 : 1;
}

__global__ void zero_deg_kernel() {
    int i = blockIdx.x * blockDim.x + threadIdx.x;
    if (i < N_NODES) g_deg[i] = 0;
}

// ---------------- edge index fetch helper ----------------
__device__ __forceinline__ int load_idx(const void* ei, long long pos) {
    if (g_is64) return (int)__ldg((const long long*)ei + pos);
    return __ldg((const int*)ei + pos);
}

// ---------------- CSR build: histogram, 3-kernel scan, fill ----------------
__global__ void __launch_bounds__(256) hist_kernel(const void* __restrict__ ei) {
    int e = blockIdx.x * blockDim.x + threadIdx.x;
    if (e >= N_EDGES) return;
    int dst = load_idx(ei, (long long)N_EDGES + e);
    atomicAdd(&g_deg[dst], 1);
}

// phase 1: per-block degree totals
__global__ void __launch_bounds__(256) csr_bsum_kernel() {
    __shared__ int sm[256];
    int t = threadIdx.x;
    int i = blockIdx.x * 256 + t;
    sm[t] = (i < N_NODES) ? g_deg[i] : 0;
    __syncthreads();
    #pragma unroll
    for (int s = 128; s > 0; s >>= 1) {
        if (t < s) sm[t] += sm[t + s];
        __syncthreads();
    }
    if (t == 0) g_bsum[blockIdx.x] = sm[0];
}

// phase 2: exclusive scan of the 196 block totals (single tiny block)
__global__ void __launch_bounds__(256) csr_bscan_kernel() {
    __shared__ int sm[256];
    int t = threadIdx.x;
    int v = (t < NB_SCAN) ? g_bsum[t] : 0;
    sm[t] = v;
    __syncthreads();
    #pragma unroll
    for (int d = 1; d < 256; d <<= 1) {
        int u = (t >= d) ? sm[t - d] : 0;
        __syncthreads();
        sm[t] += u;
        __syncthreads();
    }
    if (t < NB_SCAN) g_bpre[t] = sm[t] - v;   // exclusive prefix
    if (t == 0) g_off[N_NODES] = N_EDGES;
}

// phase 3: local scan + block prefix -> offsets
__global__ void __launch_bounds__(256) csr_offsets_kernel() {
    __shared__ int sm[256];
    int t = threadIdx.x;
    int i = blockIdx.x * 256 + t;
    int d = (i < N_NODES) ? g_deg[i] : 0;
    sm[t] = d;
    __syncthreads();
    #pragma unroll
    for (int dd = 1; dd < 256; dd <<= 1) {
        int u = (t >= dd) ? sm[t - dd] : 0;
        __syncthreads();
        sm[t] += u;
        __syncthreads();
    }
    if (i < N_NODES) {
        int off = g_bpre[blockIdx.x] + sm[t] - d;   // global exclusive prefix
        g_off[i] = off;
        g_pos[i] = off;
    }
}

__global__ void __launch_bounds__(256) fill_kernel(const void* __restrict__ ei) {
    int e = blockIdx.x * blockDim.x + threadIdx.x;
    if (e >= N_EDGES) return;
    int src = load_idx(ei, e);
    int dst = load_idx(ei, (long long)N_EDGES + e);
    int p = atomicAdd(&g_pos[dst], 1);
    g_srcs[p] = src;
}

// ---------------- CSR aggregation: gather-only, no atomics ----------------
template <int C>
__global__ void __launch_bounds__(256)
agg_csr_kernel(const float* __restrict__ feat, float* __restrict__ agg) {
    constexpr int L = C / 4;
    int gt = blockIdx.x * blockDim.x + threadIdx.x;
    int node = gt / L;
    int lane = gt % L;
    if (node >= N_NODES) return;

    int beg = g_off[node];
    int end = g_off[node + 1];
    const float4* fp = reinterpret_cast<const float4*>(feat);

    float4 a0 = make_float4(0.f, 0.f, 0.f, 0.f);
    float4 a1 = make_float4(0.f, 0.f, 0.f, 0.f);
    float4 a2 = make_float4(0.f, 0.f, 0.f, 0.f);
    float4 a3 = make_float4(0.f, 0.f, 0.f, 0.f);

    int j = beg;
    for (; j + 4 <= end; j += 4) {
        int s0 = __ldg(&g_srcs[j + 0]);
        int s1 = __ldg(&g_srcs[j + 1]);
        int s2 = __ldg(&g_srcs[j + 2]);
        int s3 = __ldg(&g_srcs[j + 3]);
        float4 v0 = __ldg(fp + (size_t)s0 * L + lane);
        float4 v1 = __ldg(fp + (size_t)s1 * L + lane);
        float4 v2 = __ldg(fp + (size_t)s2 * L + lane);
        float4 v3 = __ldg(fp + (size_t)s3 * L + lane);
        a0.x += v0.x; a0.y += v0.y; a0.z += v0.z; a0.w += v0.w;
        a1.x += v1.x; a1.y += v1.y; a1.z += v1.z; a1.w += v1.w;
        a2.x += v2.x; a2.y += v2.y; a2.z += v2.z; a2.w += v2.w;
        a3.x += v3.x; a3.y += v3.y; a3.z += v3.z; a3.w += v3.w;
    }
    for (; j < end; j++) {
        int s0 = __ldg(&g_srcs[j]);
        float4 v0 = __ldg(fp + (size_t)s0 * L + lane);
        a0.x += v0.x; a0.y += v0.y; a0.z += v0.z; a0.w += v0.w;
    }
    float4 r;
    r.x = (a0.x + a1.x) + (a2.x + a3.x);
    r.y = (a0.y + a1.y) + (a2.y + a3.y);
    r.z = (a0.z + a1.z) + (a2.z + a3.z);
    r.w = (a0.w + a1.w) + (a2.w + a3.w);
    reinterpret_cast<float4*>(agg)[(size_t)node * L + lane] = r;
}

// ---------------- fused GIN MLP (unchanged) ----------------
template <int CIN, int H, int COUT, bool RELU_OUT, int NODES>
__global__ void __launch_bounds__(512)
mlp_kernel(const float* __restrict__ x, const float* __restrict__ agg,
           const float* __restrict__ epsp,
           const float* __restrict__ Wa, const float* __restrict__ ba,
           const float* __restrict__ Wb, const float* __restrict__ bb,
           float* __restrict__ out) {
    constexpr int NPT = NODES / 32;
    constexpr int MIDS = H + 4;
    extern __shared__ float s[];
    float* Was = s;
    float* Wbs = Was + CIN * H;
    float* bas = Wbs + H * COUT;
    float* bbs = bas + H;
    float* ins = bbs + COUT;
    float* mid = ins + NODES * CIN;

    const int tid = threadIdx.x;

    for (int i = tid; i < CIN * H / 4; i += 512)
        reinterpret_cast<float4*>(Was)[i] = reinterpret_cast<const float4*>(Wa)[i];
    for (int i = tid; i < H * COUT / 4; i += 512)
        reinterpret_cast<float4*>(Wbs)[i] = reinterpret_cast<const float4*>(Wb)[i];
    if (tid < H) bas[tid] = ba[tid];
    else if (tid >= 128 && tid < 128 + COUT) bbs[tid - 128] = bb[tid - 128];

    const float epsf = 1.0f + __ldg(epsp);
    const int n0 = blockIdx.x * NODES;

    {
        constexpr int C4 = CIN / 4;
        for (int i = tid; i < NODES * C4; i += 512) {
            int n = i / C4, c4 = i - n * C4;
            int gn = n0 + n;
            float4 v = make_float4(0.f, 0.f, 0.f, 0.f);
            if (gn < N_NODES) {
                size_t g = (size_t)gn * C4 + c4;
                float4 xv = reinterpret_cast<const float4*>(x)[g];
                float4 av = reinterpret_cast<const float4*>(agg)[g];
                v.x = fmaf(epsf, xv.x, av.x);
                v.y = fmaf(epsf, xv.y, av.y);
                v.z = fmaf(epsf, xv.z, av.z);
                v.w = fmaf(epsf, xv.w, av.w);
            }
            reinterpret_cast<float4*>(ins)[n * C4 + c4] = v;
        }
    }
    __syncthreads();

    const int tx = tid & 15;
    const int ty = tid >> 4;

    {
        float acc[NPT][8];
        #pragma unroll
        for (int i = 0; i < NPT; i++)
            #pragma unroll
            for (int j = 0; j < 8; j++) acc[i][j] = 0.f;

        #pragma unroll 8
        for (int k = 0; k < CIN; k++) {
            float a[NPT];
            #pragma unroll
            for (int i = 0; i < NPT; i++) a[i] = ins[(ty * NPT + i) * CIN + k];
            float4 w0 = *reinterpret_cast<float4*>(&Was[k * H + tx * 8]);
            float4 w1 = *reinterpret_cast<float4*>(&Was[k * H + tx * 8 + 4]);
            float w[8] = {w0.x, w0.y, w0.z, w0.w, w1.x, w1.y, w1.z, w1.w};
            #pragma unroll
            for (int i = 0; i < NPT; i++)
                #pragma unroll
                for (int j = 0; j < 8; j++) acc[i][j] = fmaf(a[i], w[j], acc[i][j]);
        }
        #pragma unroll
        for (int i = 0; i < NPT; i++) {
            float4 v0, v1;
            v0.x = fmaxf(acc[i][0] + bas[tx * 8 + 0], 0.f);
            v0.y = fmaxf(acc[i][1] + bas[tx * 8 + 1], 0.f);
            v0.z = fmaxf(acc[i][2] + bas[tx * 8 + 2], 0.f);
            v0.w = fmaxf(acc[i][3] + bas[tx * 8 + 3], 0.f);
            v1.x = fmaxf(acc[i][4] + bas[tx * 8 + 4], 0.f);
            v1.y = fmaxf(acc[i][5] + bas[tx * 8 + 5], 0.f);
            v1.z = fmaxf(acc[i][6] + bas[tx * 8 + 6], 0.f);
            v1.w = fmaxf(acc[i][7] + bas[tx * 8 + 7], 0.f);
            float* row = &mid[(ty * NPT + i) * MIDS + tx * 8];
            reinterpret_cast<float4*>(row)[0] = v0;
            reinterpret_cast<float4*>(row)[1] = v1;
        }
    }
    __syncthreads();

    {
        constexpr int CPT = COUT / 16;
        float acc[NPT][CPT];
        #pragma unroll
        for (int i = 0; i < NPT; i++)
            #pragma unroll
            for (int j = 0; j < CPT; j++) acc[i][j] = 0.f;

        #pragma unroll 8
        for (int k = 0; k < H; k++) {
            float a[NPT];
            #pragma unroll
            for (int i = 0; i < NPT; i++) a[i] = mid[(ty * NPT + i) * MIDS + k];
            float w[CPT];
            #pragma unroll
            for (int q = 0; q < CPT / 4; q++) {
                float4 wq = *reinterpret_cast<float4*>(&Wbs[k * COUT + tx * CPT + q * 4]);
                w[q * 4 + 0] = wq.x; w[q * 4 + 1] = wq.y;
                w[q * 4 + 2] = wq.z; w[q * 4 + 3] = wq.w;
            }
            #pragma unroll
            for (int i = 0; i < NPT; i++)
                #pragma unroll
                for (int j = 0; j < CPT; j++) acc[i][j] = fmaf(a[i], w[j], acc[i][j]);
        }
        #pragma unroll
        for (int i = 0; i < NPT; i++) {
            int gn = n0 + ty * NPT + i;
            if (gn < N_NODES) {
                #pragma unroll
                for (int j = 0; j < CPT; j++) {
                    float v = acc[i][j] + bbs[tx * CPT + j];
                    if (RELU_OUT) v = v > 0.f ? v : 0.f;
                    out[(size_t)gn * COUT + tx * CPT + j] = v;
                }
            }
        }
    }
}

// ---------------- launch ----------------
extern "C" void kernel_launch(void* const* d_in, const int* in_sizes, int n_in,
                              void* d_out, int out_size) {
    const float* x    = (const float*)d_in[0];
    const void*  ei   = d_in[1];
    const float* W1   = (const float*)d_in[2];
    const float* b1   = (const float*)d_in[3];
    const float* W2   = (const float*)d_in[4];
    const float* b2   = (const float*)d_in[5];
    const float* eps1 = (const float*)d_in[6];
    const float* W3   = (const float*)d_in[7];
    const float* b3   = (const float*)d_in[8];
    const float* W4   = (const float*)d_in[9];
    const float* b4   = (const float*)d_in[10];
    const float* eps2 = (const float*)d_in[11];
    float* out = (float*)d_out;

    const size_t smem1 = 49920 * sizeof(float);
    const size_t smem2 = 41408 * sizeof(float);
    cudaFuncSetAttribute(mlp_kernel<64, 128, 128, true, 128>,
                         cudaFuncAttributeMaxDynamicSharedMemorySize, (int)smem1);
    cudaFuncSetAttribute(mlp_kernel<128, 128, 64, false, 64>,
                         cudaFuncAttributeMaxDynamicSharedMemorySize, (int)smem2);

    float* agg1; cudaGetSymbolAddress((void**)&agg1, g_agg1);
    float* h1;   cudaGetSymbolAddress((void**)&h1,   g_h1);
    float* agg2; cudaGetSymbolAddress((void**)&agg2, g_agg2);

    // ---- CSR build ----
    detect_kernel<<<1, 256>>>((const unsigned int*)ei);
    zero_deg_kernel<<<(N_NODES + 255) / 256, 256>>>();
    hist_kernel<<<(N_EDGES + 255) / 256, 256>>>(ei);
    csr_bsum_kernel<<<NB_SCAN, 256>>>();
    csr_bscan_kernel<<<1, 256>>>();
    csr_offsets_kernel<<<NB_SCAN, 256>>>();
    fill_kernel<<<(N_EDGES + 255) / 256, 256>>>(ei);

    // ---- layer 1 ----
    agg_csr_kernel<64><<<(N_NODES * 16 + 255) / 256, 256>>>(x, agg1);
    mlp_kernel<64, 128, 128, true, 128><<<(N_NODES + 127) / 128, 512, smem1>>>(
        x, agg1, eps1, W1, b1, W2, b2, h1);

    // ---- layer 2 ----
    agg_csr_kernel<128><<<(N_NODES * 32 + 255) / 256, 256>>>(h1, agg2);
    mlp_kernel<128, 128, 64, false, 64><<<(N_NODES + 63) / 64, 512, smem2>>>(
        h1, agg2, eps2, W3, b3, W4, b4, out);
}

// round 9
// speedup vs baseline: 2.2940x; 1.9263x over previous
#include <cuda_runtime.h>
#include <cuda_bf16.h>
#include <cstdint>
#include <cstddef>

#define N_NODES 50000
#define N_EDGES 800000
#define NB_SCAN 196

// ---------------- scratch ----------------
__device__ float g_agg1[(size_t)N_NODES * 64];
__device__ float g_h1  [(size_t)N_NODES * 128];
__device__ float g_agg2[(size_t)N_NODES * 128];
__device__ int   g_is64;
__device__ int   g_deg[N_NODES];
__device__ int   g_off[N_NODES + 1];
__device__ int   g_pos[N_NODES];
__device__ int   g_srcs[N_EDGES];
__device__ int   g_bsum[256];
__device__ int   g_bpre[256];

// ================= warp-MMA helpers (baseline PTX, sm_80+) =================
__device__ __forceinline__ uint32_t s2u(const void* p) {
    uint32_t a;
    asm("{ .reg .u64 t; cvta.to.shared.u64 t, %1; cvt.u32.u64 %0, t; }" : "=r"(a) : "l"(p));
    return a;
}
#define LDM_X4(r, a) asm volatile( \
    "ldmatrix.sync.aligned.m8n8.x4.shared.b16 {%0,%1,%2,%3}, [%4];" \
    : "=r"((r)[0]), "=r"((r)[1]), "=r"((r)[2]), "=r"((r)[3]) : "r"(a))
#define LDMT_X4(r, a) asm volatile( \
    "ldmatrix.sync.aligned.m8n8.x4.trans.shared.b16 {%0,%1,%2,%3}, [%4];" \
    : "=r"((r)[0]), "=r"((r)[1]), "=r"((r)[2]), "=r"((r)[3]) : "r"(a))
#define MMA_BF16(c, a, b0, b1) asm volatile( \
    "mma.sync.aligned.m16n8k16.row.col.f32.bf16.bf16.f32 " \
    "{%0,%1,%2,%3}, {%4,%5,%6,%7}, {%8,%9}, {%0,%1,%2,%3};" \
    : "+f"((c)[0]), "+f"((c)[1]), "+f"((c)[2]), "+f"((c)[3]) \
    : "r"((a)[0]), "r"((a)[1]), "r"((a)[2]), "r"((a)[3]), "r"(b0), "r"(b1))

__device__ __forceinline__ void split2(float v, uint16_t& h, uint16_t& l) {
    __nv_bfloat16 bh = __float2bfloat16(v);
    float r = v - __bfloat162float(bh);
    __nv_bfloat16 bl = __float2bfloat16(r);
    h = *reinterpret_cast<uint16_t*>(&bh);
    l = *reinterpret_cast<uint16_t*>(&bl);
}

// ---------------- dtype detection + CSR build (unchanged from R5) ----------
__global__ void detect_kernel(const unsigned int* __restrict__ p) {
    __shared__ int found;
    if (threadIdx.x == 0) found = 0;
    __syncthreads();
    for (int i = threadIdx.x; i < 4096; i += blockDim.x)
        if (p[2 * i + 1] != 0u) found = 1;
    __syncthreads();
    if (threadIdx.x == 0) g_is64 = found ? 0 : 1;
}
__global__ void zero_deg_kernel() {
    int i = blockIdx.x * blockDim.x + threadIdx.x;
    if (i < N_NODES) g_deg[i] = 0;
}
__device__ __forceinline__ int load_idx(const void* ei, long long pos) {
    if (g_is64) return (int)__ldg((const long long*)ei + pos);
    return __ldg((const int*)ei + pos);
}
__global__ void __launch_bounds__(256) hist_kernel(const void* __restrict__ ei) {
    int e = blockIdx.x * blockDim.x + threadIdx.x;
    if (e >= N_EDGES) return;
    atomicAdd(&g_deg[load_idx(ei, (long long)N_EDGES + e)], 1);
}
__global__ void __launch_bounds__(256) csr_bsum_kernel() {
    __shared__ int sm[256];
    int t = threadIdx.x;
    int i = blockIdx.x * 256 + t;
    sm[t] = (i < N_NODES) ? g_deg[i] : 0;
    __syncthreads();
    #pragma unroll
    for (int s = 128; s > 0; s >>= 1) {
        if (t < s) sm[t] += sm[t + s];
        __syncthreads();
    }
    if (t == 0) g_bsum[blockIdx.x] = sm[0];
}
__global__ void __launch_bounds__(256) csr_bscan_kernel() {
    __shared__ int sm[256];
    int t = threadIdx.x;
    int v = (t < NB_SCAN) ? g_bsum[t] : 0;
    sm[t] = v;
    __syncthreads();
    #pragma unroll
    for (int d = 1; d < 256; d <<= 1) {
        int u = (t >= d) ? sm[t - d] : 0;
        __syncthreads();
        sm[t] += u;
        __syncthreads();
    }
    if (t < NB_SCAN) g_bpre[t] = sm[t] - v;
    if (t == 0) g_off[N_NODES] = N_EDGES;
}
__global__ void __launch_bounds__(256) csr_offsets_kernel() {
    __shared__ int sm[256];
    int t = threadIdx.x;
    int i = blockIdx.x * 256 + t;
    int d = (i < N_NODES) ? g_deg[i] : 0;
    sm[t] = d;
    __syncthreads();
    #pragma unroll
    for (int dd = 1; dd < 256; dd <<= 1) {
        int u = (t >= dd) ? sm[t - dd] : 0;
        __syncthreads();
        sm[t] += u;
        __syncthreads();
    }
    if (i < N_NODES) {
        int off = g_bpre[blockIdx.x] + sm[t] - d;
        g_off[i] = off;
        g_pos[i] = off;
    }
}
__global__ void __launch_bounds__(256) fill_kernel(const void* __restrict__ ei) {
    int e = blockIdx.x * blockDim.x + threadIdx.x;
    if (e >= N_EDGES) return;
    int src = load_idx(ei, e);
    int dst = load_idx(ei, (long long)N_EDGES + e);
    g_srcs[atomicAdd(&g_pos[dst], 1)] = src;
}

// ---------------- CSR aggregation (unchanged from R5) ----------------
template <int C>
__global__ void __launch_bounds__(256)
agg_csr_kernel(const float* __restrict__ feat, float* __restrict__ agg) {
    constexpr int L = C / 4;
    int gt = blockIdx.x * blockDim.x + threadIdx.x;
    int node = gt / L;
    int lane = gt % L;
    if (node >= N_NODES) return;
    int beg = g_off[node];
    int end = g_off[node + 1];
    const float4* fp = reinterpret_cast<const float4*>(feat);
    float4 a0 = make_float4(0.f, 0.f, 0.f, 0.f);
    float4 a1 = a0, a2 = a0, a3 = a0;
    int j = beg;
    for (; j + 4 <= end; j += 4) {
        int s0 = __ldg(&g_srcs[j + 0]), s1 = __ldg(&g_srcs[j + 1]);
        int s2 = __ldg(&g_srcs[j + 2]), s3 = __ldg(&g_srcs[j + 3]);
        float4 v0 = __ldg(fp + (size_t)s0 * L + lane);
        float4 v1 = __ldg(fp + (size_t)s1 * L + lane);
        float4 v2 = __ldg(fp + (size_t)s2 * L + lane);
        float4 v3 = __ldg(fp + (size_t)s3 * L + lane);
        a0.x += v0.x; a0.y += v0.y; a0.z += v0.z; a0.w += v0.w;
        a1.x += v1.x; a1.y += v1.y; a1.z += v1.z; a1.w += v1.w;
        a2.x += v2.x; a2.y += v2.y; a2.z += v2.z; a2.w += v2.w;
        a3.x += v3.x; a3.y += v3.y; a3.z += v3.z; a3.w += v3.w;
    }
    for (; j < end; j++) {
        float4 v0 = __ldg(fp + (size_t)__ldg(&g_srcs[j]) * L + lane);
        a0.x += v0.x; a0.y += v0.y; a0.z += v0.z; a0.w += v0.w;
    }
    float4 r;
    r.x = (a0.x + a1.x) + (a2.x + a3.x);
    r.y = (a0.y + a1.y) + (a2.y + a3.y);
    r.z = (a0.z + a1.z) + (a2.z + a3.z);
    r.w = (a0.w + a1.w) + (a2.w + a3.w);
    reinterpret_cast<float4*>(agg)[(size_t)node * L + lane] = r;
}

// ================ warp-MMA fused GIN MLP (split-bf16, mma.sync) ============
// 128 nodes/CTA, 512 threads = 16 warps: wm = wid&7 (16-row m-tile),
// wn = wid>>3 (half of N cols). 3-product split-bf16 per K=16 step.
template <int CIN, int H, int COUT, bool RELU_OUT>
__global__ void __launch_bounds__(512)
mlp_mma_kernel(const float* __restrict__ x, const float* __restrict__ agg,
               const float* __restrict__ epsp,
               const float* __restrict__ Wa, const float* __restrict__ ba,
               const float* __restrict__ Wb, const float* __restrict__ bb,
               float* __restrict__ out) {
    constexpr int STRA = CIN + 8;     // halfs
    constexpr int STRM = H + 8;
    constexpr int STRW1 = H + 8;
    constexpr int STRW2 = COUT + 8;
    constexpr int SZ_A = 128 * STRA * 2;      // bytes per (hi or lo) plane
    constexpr int SZ_M = 128 * STRM * 2;
    constexpr int U_HALF = (SZ_A > SZ_M ? SZ_A : SZ_M);
    // byte offsets
    constexpr int SM_AHI = 0;                 // A hi  (aliased with mid hi)
    constexpr int SM_ALO = SM_AHI + SZ_A;     // A lo
    constexpr int SM_MHI = 0;                 // mid hi (aliased)
    constexpr int SM_MLO = SM_MHI + SZ_M;
    constexpr int SM_U_END = 2 * U_HALF;
    constexpr int SM_W1HI = SM_U_END;
    constexpr int SM_W1LO = SM_W1HI + CIN * STRW1 * 2;
    constexpr int SM_W2HI = SM_W1LO + CIN * STRW1 * 2;
    constexpr int SM_W2LO = SM_W2HI + H * STRW2 * 2;
    constexpr int SM_BA   = SM_W2LO + H * STRW2 * 2;
    constexpr int SM_BB   = SM_BA + H * 4;

    extern __shared__ char smem[];
    const uint32_t sb = s2u(smem);
    const int tid = threadIdx.x;
    const int wid = tid >> 5, lane = tid & 31;
    const int wm = wid & 7, wn = wid >> 3;
    const int n0 = blockIdx.x * 128;

    // ---- stage weights split hi/lo ----
    for (int i = tid; i < CIN * H; i += 512) {
        int k = i / H, n = i - k * H;       // H is pow2
        uint16_t h, l; split2(__ldg(Wa + i), h, l);
        *(uint16_t*)(smem + SM_W1HI + (k * STRW1 + n) * 2) = h;
        *(uint16_t*)(smem + SM_W1LO + (k * STRW1 + n) * 2) = l;
    }
    for (int i = tid; i < H * COUT; i += 512) {
        int k = i / COUT, n = i - k * COUT;
        uint16_t h, l; split2(__ldg(Wb + i), h, l);
        *(uint16_t*)(smem + SM_W2HI + (k * STRW2 + n) * 2) = h;
        *(uint16_t*)(smem + SM_W2LO + (k * STRW2 + n) * 2) = l;
    }
    if (tid < H) ((float*)(smem + SM_BA))[tid] = ba[tid];
    else if (tid >= 128 && tid < 128 + COUT) ((float*)(smem + SM_BB))[tid - 128] = bb[tid - 128];

    // ---- stage A = (1+eps)*x + agg, split hi/lo ----
    const float epsf = 1.0f + __ldg(epsp);
    {
        constexpr int C4 = CIN / 4;
        for (int i = tid; i < 128 * C4; i += 512) {
            int n = i / C4, c4 = (i - n * C4) * 4;
            int gn = n0 + n;
            float v[4] = {0.f, 0.f, 0.f, 0.f};
            if (gn < N_NODES) {
                size_t g = (size_t)gn * C4 + (c4 >> 2);
                float4 xv = reinterpret_cast<const float4*>(x)[g];
                float4 av = reinterpret_cast<const float4*>(agg)[g];
                v[0] = fmaf(epsf, xv.x, av.x);
                v[1] = fmaf(epsf, xv.y, av.y);
                v[2] = fmaf(epsf, xv.z, av.z);
                v[3] = fmaf(epsf, xv.w, av.w);
            }
            #pragma unroll
            for (int j = 0; j < 4; j++) {
                uint16_t h, l; split2(v[j], h, l);
                *(uint16_t*)(smem + SM_AHI + (n * STRA + c4 + j) * 2) = h;
                *(uint16_t*)(smem + SM_ALO + (n * STRA + c4 + j) * 2) = l;
            }
        }
    }
    __syncthreads();

    // per-thread ldmatrix lane addresses
    const int lrow = lane & 15, lhalf = lane >> 4;   // A: row / col-8 select
    const uint32_t aHiB = sb + SM_AHI + ((wm * 16 + lrow) * STRA + lhalf * 8) * 2;
    const uint32_t aLoB = sb + SM_ALO + ((wm * 16 + lrow) * STRA + lhalf * 8) * 2;

    // ---- GEMM1: [128 x CIN] @ [CIN x H] -> mid ----
    constexpr int NT1 = H / 16;      // n8-tiles per warp (pairs: NT1/... NT = (H/2)/8
    float acc1[NT1][4];
    #pragma unroll
    for (int t = 0; t < NT1; t++)
        #pragma unroll
        for (int j = 0; j < 4; j++) acc1[t][j] = 0.f;
    {
        const uint32_t bHiB = sb + SM_W1HI + (lrow * STRW1 + wn * (H / 2) + lhalf * 8) * 2;
        const uint32_t bLoB = sb + SM_W1LO + (lrow * STRW1 + wn * (H / 2) + lhalf * 8) * 2;
        #pragma unroll
        for (int ks = 0; ks < CIN / 16; ks++) {
            uint32_t ah[4], al[4];
            LDM_X4(ah, aHiB + ks * 32);
            LDM_X4(al, aLoB + ks * 32);
            #pragma unroll
            for (int t = 0; t < NT1 / 2; t++) {
                uint32_t bh[4], bl[4];
                uint32_t bo = ks * 16 * STRW1 * 2 + t * 32;
                LDMT_X4(bh, bHiB + bo);
                LDMT_X4(bl, bLoB + bo);
                MMA_BF16(acc1[2 * t],     ah, bh[0], bh[1]);
                MMA_BF16(acc1[2 * t],     ah, bl[0], bl[1]);
                MMA_BF16(acc1[2 * t],     al, bh[0], bh[1]);
                MMA_BF16(acc1[2 * t + 1], ah, bh[2], bh[3]);
                MMA_BF16(acc1[2 * t + 1], ah, bl[2], bl[3]);
                MMA_BF16(acc1[2 * t + 1], al, bh[2], bh[3]);
            }
        }
    }
    __syncthreads();   // all A reads done; union region can be overwritten

    // ---- epilogue1: relu(acc + ba) -> split -> mid ----
    {
        const float* bap = (const float*)(smem + SM_BA);
        const int r0 = wm * 16 + (lane >> 2);
        const int cb = wn * (H / 2) + (lane & 3) * 2;
        #pragma unroll
        for (int t = 0; t < NT1; t++) {
            int col = cb + t * 8;
            float v0 = fmaxf(acc1[t][0] + bap[col], 0.f);
            float v1 = fmaxf(acc1[t][1] + bap[col + 1], 0.f);
            float v2 = fmaxf(acc1[t][2] + bap[col], 0.f);
            float v3 = fmaxf(acc1[t][3] + bap[col + 1], 0.f);
            uint16_t h0, l0, h1, l1;
            split2(v0, h0, l0); split2(v1, h1, l1);
            *(uint32_t*)(smem + SM_MHI + (r0 * STRM + col) * 2) = (uint32_t)h0 | ((uint32_t)h1 << 16);
            *(uint32_t*)(smem + SM_MLO + (r0 * STRM + col) * 2) = (uint32_t)l0 | ((uint32_t)l1 << 16);
            split2(v2, h0, l0); split2(v3, h1, l1);
            *(uint32_t*)(smem + SM_MHI + ((r0 + 8) * STRM + col) * 2) = (uint32_t)h0 | ((uint32_t)h1 << 16);
            *(uint32_t*)(smem + SM_MLO + ((r0 + 8) * STRM + col) * 2) = (uint32_t)l0 | ((uint32_t)l1 << 16);
        }
    }
    __syncthreads();

    // ---- GEMM2: [128 x H] @ [H x COUT] -> out ----
    constexpr int NT2 = COUT / 16;
    float acc2[NT2][4];
    #pragma unroll
    for (int t = 0; t < NT2; t++)
        #pragma unroll
        for (int j = 0; j < 4; j++) acc2[t][j] = 0.f;
    {
        const uint32_t mHiB = sb + SM_MHI + ((wm * 16 + lrow) * STRM + lhalf * 8) * 2;
        const uint32_t mLoB = sb + SM_MLO + ((wm * 16 + lrow) * STRM + lhalf * 8) * 2;
        const uint32_t bHiB = sb + SM_W2HI + (lrow * STRW2 + wn * (COUT / 2) + lhalf * 8) * 2;
        const uint32_t bLoB = sb + SM_W2LO + (lrow * STRW2 + wn * (COUT / 2) + lhalf * 8) * 2;
        #pragma unroll
        for (int ks = 0; ks < H / 16; ks++) {
            uint32_t ah[4], al[4];
            LDM_X4(ah, mHiB + ks * 32);
            LDM_X4(al, mLoB + ks * 32);
            #pragma unroll
            for (int t = 0; t < NT2 / 2; t++) {
                uint32_t bh[4], bl[4];
                uint32_t bo = ks * 16 * STRW2 * 2 + t * 32;
                LDMT_X4(bh, bHiB + bo);
                LDMT_X4(bl, bLoB + bo);
                MMA_BF16(acc2[2 * t],     ah, bh[0], bh[1]);
                MMA_BF16(acc2[2 * t],     ah, bl[0], bl[1]);
                MMA_BF16(acc2[2 * t],     al, bh[0], bh[1]);
                MMA_BF16(acc2[2 * t + 1], ah, bh[2], bh[3]);
                MMA_BF16(acc2[2 * t + 1], ah, bl[2], bl[3]);
                MMA_BF16(acc2[2 * t + 1], al, bh[2], bh[3]);
            }
        }
    }

    // ---- epilogue2: acc + bb (optional relu) -> gmem ----
    {
        const float* bbp = (const float*)(smem + SM_BB);
        const int r0 = wm * 16 + (lane >> 2);
        const int cb = wn * (COUT / 2) + (lane & 3) * 2;
        #pragma unroll
        for (int t = 0; t < NT2; t++) {
            int col = cb + t * 8;
            float v0 = acc2[t][0] + bbp[col];
            float v1 = acc2[t][1] + bbp[col + 1];
            float v2 = acc2[t][2] + bbp[col];
            float v3 = acc2[t][3] + bbp[col + 1];
            if (RELU_OUT) {
                v0 = fmaxf(v0, 0.f); v1 = fmaxf(v1, 0.f);
                v2 = fmaxf(v2, 0.f); v3 = fmaxf(v3, 0.f);
            }
            int gn0 = n0 + r0, gn1 = n0 + r0 + 8;
            if (gn0 < N_NODES)
                *reinterpret_cast<float2*>(out + (size_t)gn0 * COUT + col) = make_float2(v0, v1);
            if (gn1 < N_NODES)
                *reinterpret_cast<float2*>(out + (size_t)gn1 * COUT + col) = make_float2(v2, v3);
        }
    }
}

// ---------------- launch ----------------
extern "C" void kernel_launch(void* const* d_in, const int* in_sizes, int n_in,
                              void* d_out, int out_size) {
    const float* x    = (const float*)d_in[0];
    const void*  ei   = d_in[1];
    const float* W1   = (const float*)d_in[2];
    const float* b1   = (const float*)d_in[3];
    const float* W2   = (const float*)d_in[4];
    const float* b2   = (const float*)d_in[5];
    const float* eps1 = (const float*)d_in[6];
    const float* W3   = (const float*)d_in[7];
    const float* b3   = (const float*)d_in[8];
    const float* W4   = (const float*)d_in[9];
    const float* b4   = (const float*)d_in[10];
    const float* eps2 = (const float*)d_in[11];
    float* out = (float*)d_out;

    // layer1: U=2*max(128*72,128*136)*2=69632; W1=2*64*136*2=34816;
    //         W2=2*128*136*2=69632; BA=512; BB=512  -> 175104
    // layer2: U=69632; W1=2*128*136*2=69632; W2=2*128*72*2=36864; BA=512; BB=256 -> 176896
    const int smem1 = 175104;
    const int smem2 = 176896;
    cudaFuncSetAttribute(mlp_mma_kernel<64, 128, 128, true>,
                         cudaFuncAttributeMaxDynamicSharedMemorySize, smem1);
    cudaFuncSetAttribute(mlp_mma_kernel<128, 128, 64, false>,
                         cudaFuncAttributeMaxDynamicSharedMemorySize, smem2);

    float* agg1; cudaGetSymbolAddress((void**)&agg1, g_agg1);
    float* h1;   cudaGetSymbolAddress((void**)&h1,   g_h1);
    float* agg2; cudaGetSymbolAddress((void**)&agg2, g_agg2);

    // ---- CSR build ----
    detect_kernel<<<1, 256>>>((const unsigned int*)ei);
    zero_deg_kernel<<<(N_NODES + 255) / 256, 256>>>();
    hist_kernel<<<(N_EDGES + 255) / 256, 256>>>(ei);
    csr_bsum_kernel<<<NB_SCAN, 256>>>();
    csr_bscan_kernel<<<1, 256>>>();
    csr_offsets_kernel<<<NB_SCAN, 256>>>();
    fill_kernel<<<(N_EDGES + 255) / 256, 256>>>(ei);

    const int nmb = (N_NODES + 127) / 128;   // 391

    // ---- layer 1 ----
    agg_csr_kernel<64><<<(N_NODES * 16 + 255) / 256, 256>>>(x, agg1);
    mlp_mma_kernel<64, 128, 128, true><<<nmb, 512, smem1>>>(
        x, agg1, eps1, W1, b1, W2, b2, h1);

    // ---- layer 2 ----
    agg_csr_kernel<128><<<(N_NODES * 32 + 255) / 256, 256>>>(h1, agg2);
    mlp_mma_kernel<128, 128, 64, false><<<nmb, 512, smem2>>>(
        h1, agg2, eps2, W3, b3, W4, b4, out);
}